// round 12
// baseline (speedup 1.0000x reference)
#include <cuda_runtime.h>
#include <math_constants.h>
#include <cstdint>

#define BN    8
#define BC    256
#define BNF   16
#define BWH   784            // 28*28
#define CSTR4 3136           // float4 stride between channels of l
#define NV4   196            // float4 per wh-row
#define NTILE (BN*BNF)       // 128
#define NCH   14             // wh-chunks per tile
#define CF4   14             // float4 per chunk (56 wh)
#define PAD   15             // padded row stride in f4 (conflict-free)
#define NTHR  256

#define SMEM_B (BC * PAD * 16)   // 61440 B : scache4[256][15]

// scratch — fully overwritten every run
__device__ float         d_P[NTILE][NCH][BC];   // partial pools (1.8 MB)
__device__ float         d_es[NTILE][NCH];      // partial exp-sums
__device__ unsigned int  d_cnt[NTILE];          // monotonic arrival counters

__global__ __launch_bounds__(NTHR)
void mfla_fused_kernel(const float* __restrict__ l,
                       const float* __restrict__ g,
                       const float* __restrict__ w,
                       float* __restrict__ outc,   // [N,NF,W,H]
                       float* __restrict__ outg)   // [N,C,NF]
{
    extern __shared__ __align__(16) float4 scache4[];   // [256][15] (14 used)
    __shared__ float  sw[BC];
    __shared__ __align__(16) float4 part4[16 * CF4];    // 16 cgroups x 14 pos
    __shared__ __align__(16) float4 aexp4[CF4];         // exp(c) of this chunk
    __shared__ float  red[8];
    __shared__ float  s_gdot;
    __shared__ int    s_last;

    const int tid   = threadIdx.x;
    const int tile  = blockIdx.x / NCH;      // n*16 + f
    const int chunk = blockIdx.x - tile * NCH;
    const int n     = tile >> 4;
    const int f     = tile & 15;
    const int base  = chunk * CF4;

    const float4* lb4 = reinterpret_cast<const float4*>(
        l + ((size_t)n * BC * BNF + f) * BWH);

    // ---- Phase 1: copy my chunk, one channel per thread (14 batched LDG.128) ----
    {
        const float4* src = lb4 + (size_t)tid * CSTR4 + base;
        float4* dst = scache4 + tid * PAD;
        #pragma unroll
        for (int i = 0; i < CF4; ++i) dst[i] = src[i];
    }

    // ---- gdot over all 256 channels + weights to smem (overlaps with copies) ----
    {
        float wv = w[tid];
        sw[tid] = wv;
        float p = g[n * BC + tid] * wv;
        #pragma unroll
        for (int o = 16; o; o >>= 1) p += __shfl_xor_sync(0xffffffffu, p, o);
        if ((tid & 31) == 0) red[tid >> 5] = p;
    }
    __syncthreads();
    if (tid < 8) {
        float v = red[tid];
        #pragma unroll
        for (int o = 4; o; o >>= 1) v += __shfl_xor_sync(0xffu, v, o);
        if (tid == 0) s_gdot = v;
    }
    __syncthreads();

    // ---- Phase 2: channel dot from smem: 16 cgroups x 14 positions ----
    if (tid < 16 * CF4) {
        const int cg  = tid / CF4;
        const int pos = tid - cg * CF4;
        float4 a = make_float4(0.f, 0.f, 0.f, 0.f);
        #pragma unroll
        for (int cc = 0; cc < 16; ++cc) {
            const int c = cg * 16 + cc;
            float4 v = scache4[c * PAD + pos];
            float wv = sw[c];
            a.x = fmaf(v.x, wv, a.x);
            a.y = fmaf(v.y, wv, a.y);
            a.z = fmaf(v.z, wv, a.z);
            a.w = fmaf(v.w, wv, a.w);
        }
        part4[cg * CF4 + pos] = a;
    }
    __syncthreads();

    // ---- Phase 2b: combine 16 partials, +gdot, write c, exp, partial expsum ----
    {
        float se = 0.f;
        if (tid < CF4) {
            const float gd = s_gdot;
            float4 v = make_float4(gd, gd, gd, gd);
            #pragma unroll
            for (int k = 0; k < 16; ++k) {
                float4 q = part4[k * CF4 + tid];
                v.x += q.x; v.y += q.y; v.z += q.z; v.w += q.w;
            }
            reinterpret_cast<float4*>(outc)[(size_t)tile * NV4 + base + tid] = v;
            float4 e = make_float4(__expf(v.x), __expf(v.y), __expf(v.z), __expf(v.w));
            aexp4[tid] = e;
            se = (e.x + e.y) + (e.z + e.w);
        }
        if (tid < 32) {
            #pragma unroll
            for (int o = 16; o; o >>= 1) se += __shfl_xor_sync(0xffffffffu, se, o);
            if (tid == 0) d_es[tile][chunk] = se;
        }
    }
    __syncthreads();

    // ---- Phase 3: partial pool, one channel per thread (conflict-free, PAD=15) ----
    {
        float acc = 0.f;
        const float4* row = scache4 + tid * PAD;
        #pragma unroll
        for (int i = 0; i < CF4; ++i) {
            float4 e = aexp4[i];                  // broadcast
            float4 v = row[i];
            acc += e.x * v.x + e.y * v.y + e.z * v.z + e.w * v.w;
        }
        d_P[tile][chunk][tid] = acc;              // coalesced across tid
    }

    // ---- arrival: last chunk-CTA of this tile finishes the tile ----
    __threadfence();          // release my d_P/d_es
    __syncthreads();          // all threads done before counting
    if (tid == 0) {
        unsigned int old = atomicAdd(&d_cnt[tile], 1u);
        s_last = ((old % NCH) == NCH - 1);        // replay-safe (monotonic)
    }
    __syncthreads();

    if (s_last) {
        __threadfence();      // acquire peers' d_P/d_es
        // exp-sum across 14 chunks (redundant compute, trivial)
        float s = 0.f;
        #pragma unroll
        for (int k = 0; k < NCH; ++k) s += d_es[tile][k];
        const float inv = 1.0f / s;
        // combine pools: thread = channel, 14 coalesced reads
        float a = 0.f;
        #pragma unroll
        for (int k = 0; k < NCH; ++k)
            a += __ldcg(&d_P[tile][k][tid]);
        outg[((size_t)n * BC + tid) * BNF + f] = a * inv;
    }
}

extern "C" void kernel_launch(void* const* d_in, const int* in_sizes, int n_in,
                              void* d_out, int out_size)
{
    const float* l = (const float*)d_in[0];
    const float* g = (const float*)d_in[1];
    const float* w = (const float*)d_in[2];
    float* out  = (float*)d_out;
    float* outc = out;                              // 8*16*28*28 = 100352 floats
    float* outg = out + (size_t)BN * BNF * BWH;     // 8*256*16   = 32768 floats

    cudaFuncSetAttribute(mfla_fused_kernel,
                         cudaFuncAttributeMaxDynamicSharedMemorySize, SMEM_B);
    mfla_fused_kernel<<<NTILE * NCH, NTHR, SMEM_B>>>(l, g, w, outc, outg);
}

// round 13
// speedup vs baseline: 2.8561x; 2.8561x over previous
#include <cuda_runtime.h>
#include <math_constants.h>

#define BN    8
#define BC    256
#define BNF   16
#define BWH   784            // 28*28
#define CSTR4 3136           // float4 stride between channels of l
#define NV4   196            // float4 per wh-row
#define NTILE (BN*BNF)       // 128
#define NCH   8              // wh-chunks per tile
#define K1THR 256
#define K2THR 256

// scratch — fully overwritten every run (kernel boundary orders K1->K2)
__device__ float d_P[NTILE][NCH][BC];   // unnormalized partial pools (1 MB)
__device__ float d_es[NTILE][NCH];      // partial exp-sums

// ---------------- K1: c-chunk + exp + partial pool (one launch, no sync tricks) ----
// chunk geometry, 128B-line aligned per f-parity (from R9):
//   even f: j<7 -> (24j,24), j=7 -> (168,28);  odd f: j=0 -> (0,28), j>0 -> (24j+4,24)
__global__ __launch_bounds__(K1THR)
void mfla_c_kernel(const float* __restrict__ l,
                   const float* __restrict__ g,
                   const float* __restrict__ w,
                   float* __restrict__ outc)
{
    __shared__ float sw[BC];
    __shared__ __align__(16) float4 part[8][28];
    __shared__ __align__(16) float4 aexp4[28];
    __shared__ float red[8];
    __shared__ float s_gdot;

    const int tid  = threadIdx.x;
    const int tile = blockIdx.x >> 3;      // n*16 + f
    const int j    = blockIdx.x & 7;
    const int n    = tile >> 4;
    const int f    = tile & 15;

    int start4, len4;
    if ((f & 1) == 0) { start4 = (j < 7) ? 24 * j : 168;     len4 = (j < 7) ? 24 : 28; }
    else              { start4 = (j == 0) ? 0 : 24 * j + 4;  len4 = (j == 0) ? 28 : 24; }

    const float4* lb4 = reinterpret_cast<const float4*>(
        l + ((size_t)n * BC * BNF + f) * BWH);

    // ---- weights + gdot ----
    float wv = w[tid];
    sw[tid] = wv;
    float p = g[n * BC + tid] * wv;
    #pragma unroll
    for (int o = 16; o; o >>= 1) p += __shfl_xor_sync(0xffffffffu, p, o);
    if ((tid & 31) == 0) red[tid >> 5] = p;
    __syncthreads();
    if (tid < 8) {
        float v = red[tid];
        #pragma unroll
        for (int o = 4; o; o >>= 1) v += __shfl_xor_sync(0xffu, v, o);
        if (tid == 0) s_gdot = v;
    }

    // ---- Phase 1: channel dot. 8 warps x 32 channels; lane = wh4 slot ----
    {
        const int gq = tid >> 5;
        const int s  = tid & 31;
        if (s < len4) {
            const float4* lp = lb4 + (size_t)(gq * 32) * CSTR4 + start4 + s;
            float4 a = make_float4(0.f, 0.f, 0.f, 0.f);
            #pragma unroll
            for (int c = 0; c < 32; ++c) {
                float4 v = lp[(size_t)c * CSTR4];
                float  ww = sw[gq * 32 + c];
                a.x = fmaf(v.x, ww, a.x);
                a.y = fmaf(v.y, ww, a.y);
                a.z = fmaf(v.z, ww, a.z);
                a.w = fmaf(v.w, ww, a.w);
            }
            part[gq][s] = a;
        }
    }
    __syncthreads();

    // ---- Phase 2 (warp 0 only, tid<len4<=28): combine, write c, exp, expsum ----
    if (tid < 32) {
        float se = 0.f;
        if (tid < len4) {
            const float gd = s_gdot;
            float4 v = make_float4(gd, gd, gd, gd);
            #pragma unroll
            for (int k = 0; k < 8; ++k) {
                float4 q = part[k][tid];
                v.x += q.x; v.y += q.y; v.z += q.z; v.w += q.w;
            }
            reinterpret_cast<float4*>(outc)[(size_t)tile * NV4 + start4 + tid] = v;
            float4 e = make_float4(__expf(v.x), __expf(v.y), __expf(v.z), __expf(v.w));
            aexp4[tid] = e;
            se = (e.x + e.y) + (e.z + e.w);
        }
        #pragma unroll
        for (int o = 16; o; o >>= 1) se += __shfl_xor_sync(0xffffffffu, se, o);
        if (tid == 0) d_es[tile][j] = se;
    }
    __syncthreads();

    // ---- Phase 3: partial pools. warp w owns channels [32w,32w+32); L1/L2-hot re-read ----
    {
        const int warp = tid >> 5;
        const int s    = tid & 31;
        #pragma unroll
        for (int b = 0; b < 8; ++b) {
            const int c0 = warp * 32 + b * 4;
            float acc[4] = {0.f, 0.f, 0.f, 0.f};
            if (s < len4) {
                float4 a4 = aexp4[s];
                const float4* lp = lb4 + (size_t)c0 * CSTR4 + start4 + s;
                #pragma unroll
                for (int k = 0; k < 4; ++k) {
                    float4 v = lp[(size_t)k * CSTR4];
                    acc[k] += a4.x * v.x + a4.y * v.y + a4.z * v.z + a4.w * v.w;
                }
            }
            #pragma unroll
            for (int k = 0; k < 4; ++k) {
                float a = acc[k];
                #pragma unroll
                for (int o = 16; o; o >>= 1) a += __shfl_xor_sync(0xffffffffu, a, o);
                if (s == 0) d_P[tile][j][c0 + k] = a;
            }
        }
    }
}

// ---------------- K2: tiny finisher — combine 8 partials, normalize ----------------
__global__ __launch_bounds__(K2THR)
void mfla_finish_kernel(float* __restrict__ outg)
{
    __shared__ float s_inv;
    const int tid  = threadIdx.x;
    const int tile = blockIdx.x;
    const int n    = tile >> 4;
    const int f    = tile & 15;

    if (tid == 0) {
        float s = 0.f;
        #pragma unroll
        for (int k = 0; k < NCH; ++k) s += d_es[tile][k];
        s_inv = 1.0f / s;
    }
    __syncthreads();

    float a = 0.f;
    #pragma unroll
    for (int k = 0; k < NCH; ++k) a += d_P[tile][k][tid];   // coalesced across tid
    outg[((size_t)n * BC + tid) * BNF + f] = a * s_inv;
}

extern "C" void kernel_launch(void* const* d_in, const int* in_sizes, int n_in,
                              void* d_out, int out_size)
{
    const float* l = (const float*)d_in[0];
    const float* g = (const float*)d_in[1];
    const float* w = (const float*)d_in[2];
    float* out  = (float*)d_out;
    float* outc = out;                              // 8*16*28*28 = 100352 floats
    float* outg = out + (size_t)BN * BNF * BWH;     // 8*256*16   = 32768 floats

    mfla_c_kernel     <<<NTILE * NCH, K1THR>>>(l, g, w, outc);
    mfla_finish_kernel<<<NTILE, K2THR>>>(outg);
}